// round 3
// baseline (speedup 1.0000x reference)
#include <cuda_runtime.h>
#include <cstdint>

// Problem constants
#define BATCH 64
#define TT    1000
#define NINP  64
#define HID   512
#define NACT  2

// Recurrence decomposition
#define CNC  8                    // CTAs per cluster (W_hh split 8 ways by column)
#define NB   4                    // batches per cluster
#define JPC  64                   // HID / CNC columns per CTA
#define NCLUSTER (BATCH / NB)     // 16 clusters -> 128 CTAs

// d_out layout: [out | hn_last | rnn_out]
#define HN_OFF  (BATCH * TT * NACT)
#define RNN_OFF (HN_OFF + BATCH * HID)

typedef unsigned long long u64;
typedef unsigned int u32;

// ---- packed f32x2 helpers ----
__device__ __forceinline__ u64 pk(float lo, float hi) {
    u64 r; asm("mov.b64 %0, {%1, %2};" : "=l"(r) : "f"(lo), "f"(hi)); return r;
}
__device__ __forceinline__ void upk(u64 v, float& lo, float& hi) {
    asm("mov.b64 {%0, %1}, %2;" : "=f"(lo), "=f"(hi) : "l"(v));
}
__device__ __forceinline__ u64 f2fma(u64 a, u64 b, u64 c) {
    u64 d; asm("fma.rn.f32x2 %0, %1, %2, %3;" : "=l"(d) : "l"(a), "l"(b), "l"(c));
    return d;
}

// ---- mbarrier helpers ----
#define MBINIT(addr, cnt) \
    asm volatile("mbarrier.init.shared.b64 [%0], %1;" :: "r"(addr), "r"(cnt) : "memory")
#define MB_EXPECT(addr, tx) \
    asm volatile("mbarrier.arrive.expect_tx.shared.b64 _, [%0], %1;" :: "r"(addr), "r"(tx) : "memory")
#define WAITC(addr, ph) \
    asm volatile("{\n\t.reg .pred P;\n\tWL%=:\n\t" \
                 "mbarrier.try_wait.parity.acquire.cluster.shared::cta.b64 P, [%0], %1, 0x989680;\n\t" \
                 "@!P bra WL%=;\n\t}" :: "r"(addr), "r"(ph) : "memory")

// ---------------------------------------------------------------------------
// Kernel A: inp_proj[b,t,:] = inp[b,t,:] @ W_ih  (into rnn region, in-place)
// ---------------------------------------------------------------------------
__global__ void __launch_bounds__(512, 1) k_inproj(
    const float* __restrict__ inp, const float* __restrict__ W_ih,
    float* __restrict__ rnn)
{
    __shared__ alignas(16) float2 xsp[16][NINP];   // [row_pair][k]
    const int row0 = blockIdx.x * 32;
    for (int i = threadIdx.x; i < 32 * NINP; i += 512) {
        const int r = i >> 6, k = i & 63;
        ((float*)&xsp[r >> 1][k])[r & 1] = inp[(size_t)(row0 + r) * NINP + k];
    }
    __syncthreads();

    const int j = threadIdx.x;
    u64 acc[16];
#pragma unroll
    for (int r2 = 0; r2 < 16; r2++) acc[r2] = 0ull;

#pragma unroll 8
    for (int k = 0; k < NINP; k += 2) {
        const float wa = W_ih[k * HID + j];
        const float wb = W_ih[(k + 1) * HID + j];
        const u64 w0 = pk(wa, wa), w1 = pk(wb, wb);
#pragma unroll
        for (int r2 = 0; r2 < 16; r2++) {
            const ulonglong2 hv = *reinterpret_cast<const ulonglong2*>(&xsp[r2][k]);
            acc[r2] = f2fma(hv.x, w0, acc[r2]);
            acc[r2] = f2fma(hv.y, w1, acc[r2]);
        }
    }
#pragma unroll
    for (int r2 = 0; r2 < 16; r2++) {
        float lo, hi; upk(acc[r2], lo, hi);
        rnn[(size_t)(row0 + 2 * r2) * HID + j]     = lo;
        rnn[(size_t)(row0 + 2 * r2 + 1) * HID + j] = hi;
    }
}

// ---------------------------------------------------------------------------
// Kernel B: persistent clustered recurrence.
// h state kept in k-PERMUTED layout: h_perm[buf][src_rank*256 + b*64 + jj],
// where logical k = src_rank*64 + jj. Each CTA's produced slice is therefore
// one contiguous 1KB block -> broadcast = 7 cp.async.bulk (cluster smem-smem),
// issued by one thread, complete_tx onto consumers' full barrier.
// ---------------------------------------------------------------------------
__global__ void __cluster_dims__(CNC, 1, 1) __launch_bounds__(256, 1)
k_rnn(const float* __restrict__ hn, const float* __restrict__ W_hh,
      float* __restrict__ rnn, float* __restrict__ hn_last)
{
    __shared__ alignas(16) float h_perm[2][CNC * NB * JPC];  // 2 x 8KB
    __shared__ alignas(16) float red[4][NB][JPC];            // 4KB
    __shared__ alignas(8)  u64   mb[2];                      // full[0], full[1]

    u32 rank; asm("mov.u32 %0, %%cluster_ctarank;" : "=r"(rank));
    const int cid    = blockIdx.x / CNC;
    const int b_base = cid * NB;

    const int tid = threadIdx.x;
    const int j   = tid & 63;     // local column (also epilogue jj)
    const int kg  = tid >> 6;     // k-group 0..3 (also epilogue batch)
    const int col = (int)rank * JPC + j;
    const int gb  = b_base + kg;  // epilogue batch (global)

    // Weights, permuted to match h_perm: thread covers k-groups r=2kg, 2kg+1
    // w2[r2*32 + q] = (W_hh[k][col], W_hh[k+1][col]),  k = (2kg+r2)*64 + 2q
    u64 w2[64];
#pragma unroll
    for (int r2 = 0; r2 < 2; r2++)
#pragma unroll
        for (int q = 0; q < 32; q++) {
            const int k = (2 * kg + r2) * 64 + 2 * q;
            w2[r2 * 32 + q] =
                pk(W_hh[(size_t)k * HID + col], W_hh[(size_t)(k + 1) * HID + col]);
        }

    // Prefill h_perm[0] with h0 (full permuted state for our NB batches)
    for (int i = tid; i < CNC * NB * JPC; i += 256) {
        const int r = i >> 8, b = (i >> 6) & 3, jj = i & 63;
        h_perm[0][i] = hn[(size_t)(b_base + b) * HID + r * JPC + jj];
    }

    const u32 mb_base = (u32)__cvta_generic_to_shared(&mb[0]);
    if (tid == 0) { MBINIT(mb_base, 1); MBINIT(mb_base + 8, 1); }
    __syncthreads();
    asm volatile("barrier.cluster.arrive.aligned;\n\t"
                 "barrier.cluster.wait.aligned;" ::: "memory");

    // Remote addresses (h_perm base + full-barrier base in every cluster CTA)
    const u32 hl = (u32)__cvta_generic_to_shared(&h_perm[0][0]);
    u32 rh[CNC], rm[CNC];
#pragma unroll
    for (int p = 0; p < CNC; p++) {
        asm("mapa.shared::cluster.u32 %0, %1, %2;" : "=r"(rh[p]) : "r"(hl), "r"(p));
        asm("mapa.shared::cluster.u32 %0, %1, %2;" : "=r"(rm[p]) : "r"(mb_base), "r"(p));
    }
    const u32 blk_off = (u32)rank * (NB * JPC * 4);   // our 1KB block offset
    const u32 buf_bytes = CNC * NB * JPC * 4;         // 8KB per buffer

#pragma unroll 1
    for (int t = 0; t < TT; t++) {
        const int cur = t & 1, nxt = cur ^ 1, m = t >> 1;
        const u32 wp = (u32)((cur ? m : (m + 1)) & 1);
        const size_t xoff = ((size_t)gb * TT + t) * HID + col;
        const float xv = __ldg(&rnn[xoff]);          // prefetch before wait

        if (t > 0) WAITC(mb_base + cur * 8, wp);     // h_t fully delivered
        if (tid == 0 && t < TT - 1)
            MB_EXPECT(mb_base + nxt * 8, (CNC - 1) * NB * JPC * 4);  // 7168 B

        // dot: our 2 rank-blocks are contiguous 512 floats in h_perm[cur]
        const float* hc = &h_perm[cur][0] + 2 * kg * 256;
        u64 a0 = 0ull, a1 = 0ull, a2 = 0ull, a3 = 0ull;
#pragma unroll
        for (int r2 = 0; r2 < 2; r2++) {
            const ulonglong2* hp = (const ulonglong2*)(hc + r2 * 256);
            const u64* wv = &w2[r2 * 32];
#pragma unroll
            for (int q = 0; q < 16; q++) {
                const u64 wlo = wv[2 * q], whi = wv[2 * q + 1];
                const ulonglong2 v0 = hp[0 * 16 + q];
                a0 = f2fma(v0.x, wlo, a0); a0 = f2fma(v0.y, whi, a0);
                const ulonglong2 v1 = hp[1 * 16 + q];
                a1 = f2fma(v1.x, wlo, a1); a1 = f2fma(v1.y, whi, a1);
                const ulonglong2 v2 = hp[2 * 16 + q];
                a2 = f2fma(v2.x, wlo, a2); a2 = f2fma(v2.y, whi, a2);
                const ulonglong2 v3 = hp[3 * 16 + q];
                a3 = f2fma(v3.x, wlo, a3); a3 = f2fma(v3.y, whi, a3);
            }
        }
        {
            float lo, hi;
            upk(a0, lo, hi); red[kg][0][j] = lo + hi;
            upk(a1, lo, hi); red[kg][1][j] = lo + hi;
            upk(a2, lo, hi); red[kg][2][j] = lo + hi;
            upk(a3, lo, hi); red[kg][3][j] = lo + hi;
        }
        __syncthreads();   // red[] ready; also all reads of h_perm[cur] done

        // epilogue: thread -> (batch kg, column col)
        float v = red[0][kg][j] + red[1][kg][j] + red[2][kg][j] + red[3][kg][j] + xv;
        const float hval = 1.f / (1.f + __expf(-v));
        rnn[xoff] = hval;

        if (t < TT - 1) {
            // stage into our own block of next buffer (this IS the self-copy)
            h_perm[nxt][(int)rank * 256 + kg * 64 + j] = hval;
            __syncthreads();           // staging complete before bulk reads it
            if (tid == 0) {
                asm volatile("fence.proxy.async.shared::cta;" ::: "memory");
                const u32 src = hl + (u32)nxt * buf_bytes + blk_off;
#pragma unroll
                for (int p = 0; p < CNC; p++) {
                    if (p == (int)rank) continue;
                    const u32 dst = rh[p] + (u32)nxt * buf_bytes + blk_off;
                    asm volatile(
                        "cp.async.bulk.shared::cluster.shared::cta."
                        "mbarrier::complete_tx::bytes [%0], [%1], %2, [%3];"
                        :: "r"(dst), "r"(src), "r"(NB * JPC * 4),
                           "r"(rm[p] + (u32)nxt * 8) : "memory");
                }
            }
        } else {
            hn_last[(size_t)gb * HID + col] = hval;
        }
    }
}

// ---------------------------------------------------------------------------
// Kernel C: out = sigmoid(rnn_out @ W_fc + b_fc). One warp per (b,t) row.
// ---------------------------------------------------------------------------
__global__ void __launch_bounds__(256, 8) k_fc(
    const float* __restrict__ rnn, const float* __restrict__ W_fc,
    const float* __restrict__ b_fc, float* __restrict__ out)
{
    __shared__ float wfc[HID * NACT];
    for (int i = threadIdx.x; i < HID * NACT; i += 256) wfc[i] = W_fc[i];
    __syncthreads();

    const int warp = threadIdx.x >> 5, lane = threadIdx.x & 31;
    const size_t row = (size_t)blockIdx.x * 8 + warp;
    const float4* rp = reinterpret_cast<const float4*>(rnn + row * HID);

    float a0 = 0.f, a1 = 0.f;
#pragma unroll
    for (int i = 0; i < 4; i++) {
        const float4 vv = rp[lane + 32 * i];
        const int k = (lane + 32 * i) * 4;
        a0 = fmaf(vv.x, wfc[(k + 0) * 2 + 0], a0);
        a1 = fmaf(vv.x, wfc[(k + 0) * 2 + 1], a1);
        a0 = fmaf(vv.y, wfc[(k + 1) * 2 + 0], a0);
        a1 = fmaf(vv.y, wfc[(k + 1) * 2 + 1], a1);
        a0 = fmaf(vv.z, wfc[(k + 2) * 2 + 0], a0);
        a1 = fmaf(vv.z, wfc[(k + 2) * 2 + 1], a1);
        a0 = fmaf(vv.w, wfc[(k + 3) * 2 + 0], a0);
        a1 = fmaf(vv.w, wfc[(k + 3) * 2 + 1], a1);
    }
#pragma unroll
    for (int off = 16; off > 0; off >>= 1) {
        a0 += __shfl_xor_sync(0xffffffffu, a0, off);
        a1 += __shfl_xor_sync(0xffffffffu, a1, off);
    }
    if (lane == 0) {
        out[row * NACT + 0] = 1.f / (1.f + __expf(-(a0 + b_fc[0])));
        out[row * NACT + 1] = 1.f / (1.f + __expf(-(a1 + b_fc[1])));
    }
}

// ---------------------------------------------------------------------------
extern "C" void kernel_launch(void* const* d_in, const int* in_sizes, int n_in,
                              void* d_out, int out_size)
{
    const float* inp  = (const float*)d_in[0];
    const float* hn   = (const float*)d_in[1];
    const float* W_hh = (const float*)d_in[2];
    const float* W_ih = (const float*)d_in[3];
    const float* W_fc = (const float*)d_in[4];
    const float* b_fc = (const float*)d_in[5];

    float* out = (float*)d_out;
    float* hnl = out + HN_OFF;
    float* rnn = out + RNN_OFF;

    k_inproj<<<(BATCH * TT) / 32, 512>>>(inp, W_ih, rnn);
    k_rnn<<<NCLUSTER * CNC, 256>>>(hn, W_hh, rnn, hnl);
    k_fc<<<(BATCH * TT) / 8, 256>>>(rnn, W_fc, b_fc, out);
}